// round 17
// baseline (speedup 1.0000x reference)
#include <cuda_runtime.h>
#include <cstdint>

// Problem constants
#define B_   4
#define C_   64
#define HL   64      // low-res h = w
#define HH   256     // high-res H = W
#define NPIX (HH*HH)
#define GN   (3*HH*HH)
#define INV2SS2 0.08f        // 1/(2*2.5^2)

#define ROWP 101             // padded pos stride (float4 units) per channel plane

// ---------------- scratch ----------------
__device__ float g_part[B_][64][2];          // per-block partial (sum, sumsq)

// ---------------- pre-pass: guidance sum/sumsq partials ----------------
__global__ __launch_bounds__(256) void jbu_pre(const float* __restrict__ guid) {
    const int b   = blockIdx.y;
    const int tid = threadIdx.x;
    const float* p = guid + (size_t)b * GN + (size_t)blockIdx.x * (GN / 64);
    float s = 0.f, s2 = 0.f;
    for (int i = tid; i < GN / 64; i += 256) {
        float v = p[i];
        s += v; s2 += v * v;
    }
    #pragma unroll
    for (int o = 16; o; o >>= 1) {
        s  += __shfl_xor_sync(0xffffffffu, s,  o);
        s2 += __shfl_xor_sync(0xffffffffu, s2, o);
    }
    __shared__ float sh[8][2];
    const int w = tid >> 5;
    if ((tid & 31) == 0) { sh[w][0] = s; sh[w][1] = s2; }
    __syncthreads();
    if (tid == 0) {
        float ts = 0.f, ts2 = 0.f;
        #pragma unroll
        for (int i = 0; i < 8; i++) { ts += sh[i][0]; ts2 += sh[i][1]; }
        g_part[b][blockIdx.x][0] = ts;
        g_part[b][blockIdx.x][1] = ts2;
    }
}

// ---------------- main JBU kernel ----------------
// Block: 256 threads = (r 0..3, col 0..63), 1 pixel x 64 ch per thread.
// Tile: 4 rows x 64 cols (16 cells). Grid: (HH/64=4, HH/4=64, B)
// Phase 2: chunks of 2 channel-groups (2 independent LDS streams, 4 acc chains).
// launch_bounds(256,4): 64-reg budget = R7 shape + 16 regs of pipelining headroom.
__global__ __launch_bounds__(256, 4) void jbu_main(
    const float* __restrict__ guid,   // (4,3,256,256)
    const float* __restrict__ src,    // (4,64,64,64) raw channel-major
    float* __restrict__ out)          // (4,64,256,256)
{
    __shared__ __align__(16) float s_src[16 * ROWP * 4];   // [plane][pos] f4-interleaved
    __shared__ float s_gl[3][5][20];
    __shared__ float s_inv;

    const int b     = blockIdx.z;
    const int cellY = blockIdx.y;         // 0..63
    const int cx0   = blockIdx.x * 16;    // first low-res cell x
    const int x0    = cx0 * 4;

    const int tid = threadIdx.x;

    // ---- stage source tile straight from raw gmem ----
    for (int i = tid; i < 6400; i += 256) {
        int c   = i / 100;
        int pos = i - c * 100;
        int yl  = pos / 20, xl = pos - yl * 20;
        int yi  = min(max(cellY + yl - 2, 0), HL - 1);
        int xi  = min(max(cx0   + xl - 2, 0), HL - 1);
        float v = src[(((size_t)b * C_ + c) * HL + yi) * HL + xi];
        s_src[(((c >> 2) * ROWP) + pos) * 4 + (c & 3)] = v;
    }

    // ---- stage g_low tile ----
    for (int i = tid; i < 300; i += 256) {
        int c  = i / 100;
        int rm = i - c * 100;
        int yl = rm / 20, xl = rm - yl * 20;
        int yi = min(max(cellY + yl - 2, 0), HL - 1);
        int xi = min(max(cx0   + xl - 2, 0), HL - 1);
        s_gl[c][yl][xl] =
            guid[(((size_t)b * 3 + c) * HH + (4 * yi + 2)) * HH + (4 * xi + 2)];
    }

    // ---- sigma finalization (warp 0, deterministic double shfl-tree) ----
    if (tid < 32) {
        double s  = (double)g_part[b][2 * tid][0] + (double)g_part[b][2 * tid + 1][0];
        double s2 = (double)g_part[b][2 * tid][1] + (double)g_part[b][2 * tid + 1][1];
        #pragma unroll
        for (int o = 16; o; o >>= 1) {
            s  += __shfl_xor_sync(0xffffffffu, s,  o);
            s2 += __shfl_xor_sync(0xffffffffu, s2, o);
        }
        if (tid == 0) {
            const double N = (double)GN;
            double var = (s2 - s * s / N) / (N - 1.0);
            s_inv = (float)(2.0 / var);   // 1/(2*(0.5*sigma)^2) = 2/var
        }
    }
    __syncthreads();

    // ---- phase 1: per-pixel normalized weights (25 floats in registers) ----
    const int r   = tid >> 6;        // 0..3
    const int col = tid & 63;        // 0..63
    const int y   = cellY * 4 + r;
    const int x   = x0 + col;
    const int clx = col >> 2;        // cell 0..15
    const float inv2sr2 = s_inv;

    const float g0 = guid[(((size_t)b * 3 + 0) * HH + y) * HH + x];
    const float g1 = guid[(((size_t)b * 3 + 1) * HH + y) * HH + x];
    const float g2 = guid[(((size_t)b * 3 + 2) * HH + y) * HH + x];

    float w[25];
    float den = 0.f;
    #pragma unroll
    for (int dy = 0; dy < 5; dy++) {
        #pragma unroll
        for (int dx = 0; dx < 5; dx++) {
            const int t  = dy * 5 + dx;
            const int xl = clx + dx;
            float d0 = g0 - s_gl[0][dy][xl];
            float d1 = g1 - s_gl[1][dy][xl];
            float d2 = g2 - s_gl[2][dy][xl];
            float diff2 = d0 * d0 + d1 * d1 + d2 * d2;
            float sp2 = (float)((dy - 2) * (dy - 2) + (dx - 2) * (dx - 2));
            float wt = __expf(-sp2 * INV2SS2 - diff2 * inv2sr2);
            w[t]  = wt;
            den  += wt;
        }
    }
    const float invden = 1.0f / (den + 1e-8f);
    #pragma unroll
    for (int t = 0; t < 25; t++) w[t] *= invden;

    // ---- phase 2: 8 chunks x 2 channel-groups; lanes = channel pairs ----
    float* op = out + (((size_t)b * C_) * HH + y) * HH + x;
    const ulonglong2* ps = (const ulonglong2*)s_src + clx;

    #pragma unroll 1
    for (int cgc = 0; cgc < 8; cgc++) {
        const ulonglong2* pA = ps + (size_t)(2 * cgc) * ROWP;
        const ulonglong2* pB = pA + ROWP;

        unsigned long long a0 = 0ULL, a1 = 0ULL, b0 = 0ULL, b1 = 0ULL;
        #pragma unroll
        for (int dy = 0; dy < 5; dy++) {
            #pragma unroll
            for (int dx = 0; dx < 5; dx++) {
                const int t = dy * 5 + dx;
                unsigned long long wx;
                asm("mov.b64 %0, {%1, %1};" : "=l"(wx) : "f"(w[t]));
                ulonglong2 sA = pA[dy * 20 + dx];   // cg A: {c0,c1},{c2,c3}
                ulonglong2 sB = pB[dy * 20 + dx];   // cg B
                asm("fma.rn.f32x2 %0, %1, %2, %0;" : "+l"(a0) : "l"(wx), "l"(sA.x));
                asm("fma.rn.f32x2 %0, %1, %2, %0;" : "+l"(a1) : "l"(wx), "l"(sA.y));
                asm("fma.rn.f32x2 %0, %1, %2, %0;" : "+l"(b0) : "l"(wx), "l"(sB.x));
                asm("fma.rn.f32x2 %0, %1, %2, %0;" : "+l"(b1) : "l"(wx), "l"(sB.y));
            }
        }

        float v0, v1, v2, v3, u0, u1, u2, u3;
        asm("mov.b64 {%0, %1}, %2;" : "=f"(v0), "=f"(v1) : "l"(a0));
        asm("mov.b64 {%0, %1}, %2;" : "=f"(v2), "=f"(v3) : "l"(a1));
        asm("mov.b64 {%0, %1}, %2;" : "=f"(u0), "=f"(u1) : "l"(b0));
        asm("mov.b64 {%0, %1}, %2;" : "=f"(u2), "=f"(u3) : "l"(b1));
        float* oA = op + (size_t)(8 * cgc) * NPIX;
        oA[0 * (size_t)NPIX] = v0;
        oA[1 * (size_t)NPIX] = v1;
        oA[2 * (size_t)NPIX] = v2;
        oA[3 * (size_t)NPIX] = v3;
        oA[4 * (size_t)NPIX] = u0;
        oA[5 * (size_t)NPIX] = u1;
        oA[6 * (size_t)NPIX] = u2;
        oA[7 * (size_t)NPIX] = u3;
    }
}

// ---------------- launch ----------------
extern "C" void kernel_launch(void* const* d_in, const int* in_sizes, int n_in,
                              void* d_out, int out_size) {
    const float* src  = (const float*)d_in[0];
    const float* guid = (const float*)d_in[1];
    if (n_in >= 2 && in_sizes[0] == B_ * GN) {
        const float* tmp = src; src = guid; guid = tmp;
    }
    float* out = (float*)d_out;

    jbu_pre<<<dim3(64, B_), 256>>>(guid);
    jbu_main<<<dim3(HH / 64, HH / 4, B_), 256>>>(guid, src, out);
}